// round 14
// baseline (speedup 1.0000x reference)
#include <cuda_runtime.h>

#define B_    16
#define N_    2048
#define D_    1024
#define KH    15
#define KL    5
#define ROWS  320      // B_*KH + B_*KL
#define HROWS 240      // B_*KH
#define SPLITK 16
#define KC    (D_ / SPLITK)   // 64

#define SELBLK  32
#define NGEMMB  116
#define GRID_   148            // one block per SM
#define NTASK   (25 * SPLITK)  // 400
#define BKK     8              // k-slab per double-buffer stage
#define RST     72             // padded row stride (floats) for smem slabs
#define GFL     2304           // floats per group: 2 bufs x (A+B) x 8 x 72
#define LCAP    2048           // selection candidate list (>= bag size)

// ---------------- scratch (no allocations allowed) ----------------
__device__ unsigned int g_pmax[B_];
__device__ float        g_psum[B_];
__device__ int          g_idx[ROWS];
__device__ int          g_val[ROWS];
__device__ int          g_lab[ROWS];
__device__ __align__(16) float g_Gk[SPLITK][ROWS * ROWS];
__device__ float        g_per[ROWS];
__device__ int          g_seldone;  // selection-ready counter
__device__ int          g_bar;      // gemm->loss grid barrier
__device__ int          g_cnt;      // completion counter (counts ALL blocks)

// ---------------- helpers ----------------
__device__ __forceinline__ unsigned long long f32x2_fma(unsigned long long c,
                                                        unsigned long long a,
                                                        unsigned long long b) {
    asm("fma.rn.f32x2 %0, %1, %2, %0;" : "+l"(c) : "l"(a), "l"(b));
    return c;
}

__device__ __forceinline__ unsigned long long dup_f32(float x) {
    unsigned long long r;
    unsigned u = __float_as_uint(x);
    asm("mov.b64 %0, {%1, %1};" : "=l"(r) : "r"(u));
    return r;
}

__device__ __forceinline__ int ld_cg(const int* p) {
    int v;
    asm volatile("ld.global.cg.b32 %0, [%1];" : "=r"(v) : "l"(p));
    return v;
}

// column pad: +4 words per 32 -> 8-column groups hit disjoint bank quads
__device__ __forceinline__ int padc(int c) { return c + ((c >> 5) << 2); }

// ===== ONE kernel, 148 blocks (1/SM):
//   blocks 0-31   : selection (HIGH bags 0-15, LOW bags 0-15)
//   blocks 32-147 : gram GEMM, 4 x 64-thread groups per block, 400 tasks
//   grid barrier  : then loss (each block 2-3 queries), last block finishes.
// Selection is barrier-free (each block streams all scores for the global
// bound) and uses parallel counting-rank (R13, proven).
__global__ void __launch_bounds__(256)
k_all(const float* __restrict__ fea, const float* __restrict__ score,
      const int* __restrict__ label, const float* __restrict__ t_logit,
      const float* __restrict__ ori, const float* __restrict__ l2w,
      float* __restrict__ out) {
    // big union: GEMM slabs (4 groups x 9216B = 36864B) / selection list (16KB)
    __shared__ __align__(16) float SMU[4 * GFL];
    __shared__ unsigned s_r[8];
    __shared__ float    s_bsum[8];
    __shared__ unsigned s_bmax[8];
    __shared__ int      s_red[8];
    __shared__ int      s_cnt;
    __shared__ float    red[16];
    __shared__ int      s_last;
    __shared__ float    s_c[B_], s_ce[B_];
    int bid = blockIdx.x, tid = threadIdx.x;
    int lane = tid & 31, warp = tid >> 5;

    if (bid < SELBLK) {
        // ================== selection (R13 counting-rank) ==================
        unsigned long long* s_list = (unsigned long long*)SMU;
        bool isHigh = bid < B_;
        int b = isHigh ? bid : bid - B_;

        const float4* s4 = (const float4*)score;
        unsigned gbv = isHigh ? 0u : 0xFFFFFFFFu;   // score >= 0 -> bits monotonic
#pragma unroll 16
        for (int i = 0; i < (B_ * N_ / 4) / 256; i++) {
            float4 v = s4[tid + i * 256];
            unsigned b0 = __float_as_uint(v.x), b1 = __float_as_uint(v.y);
            unsigned b2 = __float_as_uint(v.z), b3 = __float_as_uint(v.w);
            if (isHigh) gbv = max(max(gbv, b0), max(b1, max(b2, b3)));
            else        gbv = min(min(gbv, b0), min(b1, min(b2, b3)));
        }
        gbv = isHigh ? __reduce_max_sync(0xffffffffu, gbv)
                     : __reduce_min_sync(0xffffffffu, gbv);
        if (lane == 0) s_r[warp] = gbv;

        float sc[8];
#pragma unroll
        for (int i = 0; i < 8; i++) sc[i] = score[b * N_ + tid + i * 256];

        if (isHigh) {
            float s = 0.f;
            unsigned mx = 0u;
#pragma unroll
            for (int i = 0; i < 8; i++) {
                s += sc[i];
                mx = max(mx, __float_as_uint(sc[i]));
            }
#pragma unroll
            for (int o = 16; o; o >>= 1)
                s += __shfl_down_sync(0xffffffffu, s, o);
            mx = __reduce_max_sync(0xffffffffu, mx);
            if (lane == 0) { s_bsum[warp] = s; s_bmax[warp] = mx; }
        }
        if (tid == 0) s_cnt = 0;
        __syncthreads();

        unsigned gbound = isHigh ? 0u : 0xFFFFFFFFu;
#pragma unroll
        for (int w = 0; w < 8; w++)
            gbound = isHigh ? max(gbound, s_r[w]) : min(gbound, s_r[w]);

        if (isHigh && tid == 0) {
            float s = 0.f;
            unsigned mx = 0u;
#pragma unroll
            for (int w = 0; w < 8; w++) { s += s_bsum[w]; mx = max(mx, s_bmax[w]); }
            g_psum[b] = s;
            g_pmax[b] = mx;
        }

        float lo, hi;
        if (isHigh) { hi = __uint_as_float(gbound); lo = hi - 0.3f; }
        else        { lo = __uint_as_float(gbound); hi = lo + 1e-9f; }

        int myT = 0;
#pragma unroll
        for (int i = 0; i < 8; i++) myT += (sc[i] >= lo && sc[i] <= hi);
        {
            int w = __reduce_add_sync(0xffffffffu, myT);
            if (lane == 0) s_red[warp] = w;
            __syncthreads();
            if (tid == 0) {
                int t = 0;
#pragma unroll
                for (int ww = 0; ww < 8; ww++) t += s_red[ww];
                s_red[0] = t;
            }
            __syncthreads();
        }
        int T = s_red[0];
        int kneed = isHigh ? KH : 10;
        int target = min(T, kneed);

        float hi2 = hi;
        if (isHigh && T > 0) {
            float delta = 0.3f * 24.f / (float)T;
            for (;;) {
                hi2 = fminf(hi, lo + delta);
                int mc = 0;
#pragma unroll
                for (int i = 0; i < 8; i++) mc += (sc[i] >= lo && sc[i] <= hi2);
                int w = __reduce_add_sync(0xffffffffu, mc);
                if (lane == 0) s_red[warp] = w;
                __syncthreads();
                if (tid == 0) {
                    int t = 0;
#pragma unroll
                    for (int ww = 0; ww < 8; ww++) t += s_red[ww];
                    s_red[1] = t;
                }
                __syncthreads();
                if (s_red[1] >= target || hi2 >= hi) break;
                delta *= 4.f;
                __syncthreads();
            }
        }

#pragma unroll
        for (int i = 0; i < 8; i++) {
            if (sc[i] >= lo && sc[i] <= hi2) {
                int pos = atomicAdd(&s_cnt, 1);
                s_list[pos] =
                    ((unsigned long long)__float_as_uint(sc[i]) << 32) |
                    (unsigned)(tid + i * 256);
            }
        }
        __syncthreads();
        int C = s_cnt;

        int labb = isHigh ? label[b] : 2;           // 2 = N_CLASSES
        if (isHigh) {
            if (tid < KH) {
                int r = b * KH + tid;
                g_lab[r] = labb;
                if (tid >= target) { g_val[r] = 0; g_idx[r] = 0; }
                else               { g_val[r] = 1; }
            }
        } else {
            int sl = (target + 1) >> 1;
            if (tid < KL) {
                int r = HROWS + b * KL + tid;
                g_lab[r] = 2;
                if (tid >= sl) { g_val[r] = 0; g_idx[r] = 0; }
                else           { g_val[r] = 1; }
            }
        }

        for (int i = tid; i < C; i += 256) {
            unsigned long long k = s_list[i];
            int r = 0;
            for (int j = 0; j < C; j++) r += (s_list[j] < k);
            int idx = b * N_ + (int)(k & 0xFFFFFFFFULL);
            if (isHigh) {
                if (r < KH) g_idx[b * KH + r] = idx;
            } else {
                if (r < 10 && !(r & 1)) g_idx[HROWS + b * KL + (r >> 1)] = idx;
            }
        }

        __syncthreads();
        if (tid == 0) {
            __threadfence();
            atomicAdd(&g_seldone, 1);
        }
    } else {
        // ================== gram GEMM (blocks 32..147) ==================
        // 4 groups of 64 threads; group g of block b handles task
        //   gid = (b-32) + 116*g  (gid < 400), task = 64x64 tile x K-slab.
        if (tid == 0) {
            while (ld_cg(&g_seldone) < SELBLK) { __nanosleep(32); }
            __threadfence();
        }
        __syncthreads();

        int grp = tid >> 6, gtid = tid & 63;
        int gid = (bid - SELBLK) + NGEMMB * grp;
        if (gid < NTASK) {
            int tile = gid >> 4, kz = gid & (SPLITK - 1);
            int bm = tile / 5, bn = tile % 5;
            int tx = gtid & 7, ty = gtid >> 3;

            float* Ab = SMU + grp * GFL;             // [2][8][72]
            float* Bb = Ab + 2 * BKK * RST;          // [2][8][72]
            int rp = padc(gtid);                     // this thread's store col
            int typ = padc(ty * 8);                  // A-frag phys col base
            int txp = padc(tx * 8);                  // B-frag phys col base

            // row pointers (one gmem row per thread), indirect gather
            const float4* pa = (const float4*)(fea +
                (size_t)g_idx[bm * 64 + gtid] * D_ + kz * KC);
            const float4* pb = (const float4*)(fea +
                (size_t)g_idx[bn * 64 + gtid] * D_ + kz * KC);

            unsigned long long cc[8][4];
#pragma unroll
            for (int i = 0; i < 8; i++)
#pragma unroll
                for (int j = 0; j < 4; j++) cc[i][j] = 0ULL;

            // initial slab (it = 0) -> buffer 0
            float4 a0 = pa[0], a1 = pa[1], b0 = pb[0], b1 = pb[1];
            {
                float av[8] = {a0.x, a0.y, a0.z, a0.w, a1.x, a1.y, a1.z, a1.w};
                float bv[8] = {b0.x, b0.y, b0.z, b0.w, b1.x, b1.y, b1.z, b1.w};
#pragma unroll
                for (int k = 0; k < 8; k++) {
                    Ab[k * RST + rp] = av[k];
                    Bb[k * RST + rp] = bv[k];
                }
            }
            asm volatile("bar.sync %0, 64;" :: "r"(grp + 1) : "memory");

#pragma unroll
            for (int it = 0; it < KC / BKK; it++) {
                int cur = it & 1;
                if (it < KC / BKK - 1) {             // prefetch next slab
                    a0 = pa[(it + 1) * 2];
                    a1 = pa[(it + 1) * 2 + 1];
                    b0 = pb[(it + 1) * 2];
                    b1 = pb[(it + 1) * 2 + 1];
                }
                const float* Ar = Ab + cur * BKK * RST;
                const float* Br = Bb + cur * BKK * RST;
#pragma unroll
                for (int k = 0; k < BKK; k++) {
                    float4 alo = *(const float4*)(Ar + k * RST + typ);
                    float4 ahi = *(const float4*)(Ar + k * RST + typ + 4);
                    longlong2 blo = *(const longlong2*)(Br + k * RST + txp);
                    longlong2 bhi = *(const longlong2*)(Br + k * RST + txp + 4);
                    unsigned long long bp0 = (unsigned long long)blo.x;
                    unsigned long long bp1 = (unsigned long long)blo.y;
                    unsigned long long bp2 = (unsigned long long)bhi.x;
                    unsigned long long bp3 = (unsigned long long)bhi.y;
                    float av[8] = {alo.x, alo.y, alo.z, alo.w,
                                   ahi.x, ahi.y, ahi.z, ahi.w};
#pragma unroll
                    for (int i = 0; i < 8; i++) {
                        unsigned long long ad = dup_f32(av[i]);
                        cc[i][0] = f32x2_fma(cc[i][0], ad, bp0);
                        cc[i][1] = f32x2_fma(cc[i][1], ad, bp1);
                        cc[i][2] = f32x2_fma(cc[i][2], ad, bp2);
                        cc[i][3] = f32x2_fma(cc[i][3], ad, bp3);
                    }
                }
                if (it < KC / BKK - 1) {
                    // store prefetch into the OTHER buffer (not being read)
                    float* Aw = Ab + (cur ^ 1) * BKK * RST;
                    float* Bw = Bb + (cur ^ 1) * BKK * RST;
                    float av[8] = {a0.x, a0.y, a0.z, a0.w, a1.x, a1.y, a1.z, a1.w};
                    float bv[8] = {b0.x, b0.y, b0.z, b0.w, b1.x, b1.y, b1.z, b1.w};
#pragma unroll
                    for (int k = 0; k < 8; k++) {
                        Aw[k * RST + rp] = av[k];
                        Bw[k * RST + rp] = bv[k];
                    }
                    asm volatile("bar.sync %0, 64;" :: "r"(grp + 1) : "memory");
                }
            }

            // epilogue: write 8x8 block (two 16B stores per row)
            float* og = g_Gk[kz];
#pragma unroll
            for (int i = 0; i < 8; i++) {
                int row = bm * 64 + ty * 8 + i;
                float* dst = og + (size_t)row * ROWS + bn * 64 + tx * 8;
                longlong2 v0; v0.x = (long long)cc[i][0]; v0.y = (long long)cc[i][1];
                longlong2 v1; v1.x = (long long)cc[i][2]; v1.y = (long long)cc[i][3];
                *(longlong2*)dst = v0;
                *(longlong2*)(dst + 4) = v1;
            }
        }
    }

    // ================== grid barrier over all GRID_ blocks ==================
    __syncthreads();
    if (tid == 0) {
        __threadfence();
        atomicAdd(&g_bar, 1);
        while (ld_cg(&g_bar) < GRID_) { __nanosleep(32); }
        __threadfence();
    }
    __syncthreads();

    // ============ loss phase: block handles queries bid, bid+148, bid+296 ===
    for (int q = bid; q < ROWS; q += GRID_) {
        int labq = g_lab[q];
        float den = 0.f, num = 0.f;
        for (int n = tid; n < ROWS; n += 256) {
            float g = 0.f;
#pragma unroll
            for (int s = 0; s < SPLITK; s++) g += g_Gk[s][q * ROWS + n];
            float e = __expf(g * 0.0625f);          // TAU = 16
            e = g_val[n] ? e : 0.f;
            den += e;
            if (g_lab[n] == labq) num += e;
        }
#pragma unroll
        for (int o = 16; o; o >>= 1) {
            den += __shfl_down_sync(0xffffffffu, den, o);
            num += __shfl_down_sync(0xffffffffu, num, o);
        }
        if (lane == 0) { red[warp] = den; red[8 + warp] = num; }
        __syncthreads();
        if (tid == 0) {
            float d = 0.f, nm = 0.f;
#pragma unroll
            for (int w = 0; w < 8; w++) { d += red[w]; nm += red[8 + w]; }
            g_per[q] = g_val[q] ? -__logf(nm / d) : 0.f;
        }
        __syncthreads();
    }

    // ================== completion counter over ALL blocks =================
    if (tid == 0) {
        __threadfence();
        int o = atomicAdd(&g_cnt, 1);
        s_last = (o == GRID_ - 1);     // globally last -> all g_per visible
    }
    __syncthreads();

    if (s_last) {
        __threadfence();
        if (tid < B_) {
            int b = tid;
            float s = 0.f; int c = 0;
            for (int k = 0; k < KH; k++) { int r = b * KH + k; s += g_per[r]; c += g_val[r]; }
            for (int k = 0; k < KL; k++) { int r = HROWS + b * KL + k; s += g_per[r]; c += g_val[r]; }
            s_c[b] = s / (float)c;
            float se = __expf(ori[b * 2 + 0]) + __expf(ori[b * 2 + 1]);
            s_ce[b] = -__logf(__expf(t_logit[0]) / se);
        }
        __syncthreads();
        if (tid == 0) {
            float contr = 0.f, ce = 0.f;
#pragma unroll
            for (int b = 0; b < B_; b++) { contr += s_c[b]; ce += s_ce[b]; }
            contr /= (float)B_;
            ce /= (float)B_;

            unsigned mx = 0u;
            float sum = 0.f;
#pragma unroll
            for (int i = 0; i < B_; i++) { mx = max(mx, g_pmax[i]); sum += g_psum[i]; }
            float gmax = __uint_as_float(mx);
            float meanv = sum / (float)(B_ * N_);
            float Dm = meanv / gmax;
            float l2 = 0.0001f * (1.f - Dm) * (1.f - Dm) * l2w[0];

            out[0] = contr + ce + l2;
            // everyone has passed g_bar and g_seldone -> safe to reset:
            g_seldone = 0;
            g_bar = 0;
            g_cnt = 0;
            __threadfence();
        }
    }
}

// ---------------- launch ----------------
extern "C" void kernel_launch(void* const* d_in, const int* in_sizes, int n_in,
                              void* d_out, int out_size) {
    const float* fea     = (const float*)d_in[0];
    const float* score   = (const float*)d_in[1];
    const int*   label   = (const int*)d_in[2];
    const float* t_logit = (const float*)d_in[3];
    const float* ori     = (const float*)d_in[4];
    const float* l2w     = (const float*)d_in[5];
    float* out = (float*)d_out;

    k_all<<<GRID_, 256>>>(fea, score, label, t_logit, ori, l2w, out);
}

// round 15
// speedup vs baseline: 1.2490x; 1.2490x over previous
#include <cuda_runtime.h>

#define B_    16
#define N_    2048
#define D_    1024
#define KH    15
#define KL    5
#define ROWS  320      // B_*KH + B_*KL
#define HROWS 240      // B_*KH
#define SPLITK 16
#define KC    (D_ / SPLITK)   // 64

#define BM 64
#define BN 64
#define BK 16
#define SELBLK 32
#define GEMMBLK (25 * SPLITK)             // 400
#define GRID_ (SELBLK + GEMMBLK)          // 432
#define LCAP 2048                          // >= bag size: gather can't overflow
#define TASKS_PER_ROW (5 * SPLITK)         // 80 tasks complete a 64-row stripe

// ---------------- scratch (no allocations allowed) ----------------
__device__ unsigned int g_pmax[B_];
__device__ float        g_psum[B_];
__device__ int          g_idx[ROWS];
__device__ int          g_val[ROWS];
__device__ int          g_lab[ROWS];
__device__ __align__(16) float g_Gk[SPLITK][ROWS * ROWS];
__device__ float        g_per[ROWS];
__device__ int          g_seldone;    // selection-ready counter
__device__ int          g_rowcnt[5];  // per-64-row-stripe GEMM completion
__device__ int          g_cnt;        // completion counter (ALL blocks)

// ---------------- helpers ----------------
__device__ __forceinline__ unsigned long long f32x2_fma(unsigned long long c,
                                                        unsigned long long a,
                                                        unsigned long long b) {
    asm("fma.rn.f32x2 %0, %1, %2, %0;" : "+l"(c) : "l"(a), "l"(b));
    return c;
}

__device__ __forceinline__ unsigned long long dup_f32(float x) {
    unsigned long long r;
    unsigned u = __float_as_uint(x);
    asm("mov.b64 %0, {%1, %1};" : "=l"(r) : "r"(u));
    return r;
}

__device__ __forceinline__ int ld_cg(const int* p) {
    int v;
    asm volatile("ld.global.cg.b32 %0, [%1];" : "=r"(v) : "l"(p));
    return v;
}

// ===== ONE kernel: selection (0-31) | gemm (32-431) | per-stripe release |
//       loss (0-319) | last-block final scalar.
// Selection is barrier-free (each block streams all scores for the global
// bound) and uses parallel counting-rank (R13, proven). The gemm->loss
// dependency is per-64-row-stripe: loss block q waits only for the 80 tasks
// covering rows [64*(q>>6), 64*(q>>6)+63], overlapping loss with gemm tail.
__global__ void __launch_bounds__(256, 3)
k_all(const float* __restrict__ fea, const float* __restrict__ score,
      const int* __restrict__ label, const float* __restrict__ t_logit,
      const float* __restrict__ ori, const float* __restrict__ l2w,
      float* __restrict__ out) {
    __shared__ __align__(16) float As[2][BK][BM + 4];
    __shared__ __align__(16) float Bs[2][BK][BN + 4];
    __shared__ unsigned long long s_list[LCAP];
    __shared__ unsigned s_r[8];
    __shared__ float    s_bsum[8];
    __shared__ unsigned s_bmax[8];
    __shared__ int      s_red[8];
    __shared__ int      s_cnt;
    __shared__ float    red[16];
    __shared__ int      s_last;
    __shared__ float    s_c[B_], s_ce[B_];
    int bid = blockIdx.x, tid = threadIdx.x;
    int lane = tid & 31, warp = tid >> 5;

    if (bid < SELBLK) {
        // ================== selection (R13 counting-rank) ==================
        bool isHigh = bid < B_;
        int b = isHigh ? bid : bid - B_;

        const float4* s4 = (const float4*)score;
        unsigned gbv = isHigh ? 0u : 0xFFFFFFFFu;   // score >= 0 -> bits monotonic
#pragma unroll 16
        for (int i = 0; i < (B_ * N_ / 4) / 256; i++) {  // 32 float4 / thread
            float4 v = s4[tid + i * 256];
            unsigned b0 = __float_as_uint(v.x), b1 = __float_as_uint(v.y);
            unsigned b2 = __float_as_uint(v.z), b3 = __float_as_uint(v.w);
            if (isHigh) gbv = max(max(gbv, b0), max(b1, max(b2, b3)));
            else        gbv = min(min(gbv, b0), min(b1, min(b2, b3)));
        }
        gbv = isHigh ? __reduce_max_sync(0xffffffffu, gbv)
                     : __reduce_min_sync(0xffffffffu, gbv);
        if (lane == 0) s_r[warp] = gbv;

        float sc[8];
#pragma unroll
        for (int i = 0; i < 8; i++) sc[i] = score[b * N_ + tid + i * 256];

        if (isHigh) {
            float s = 0.f;
            unsigned mx = 0u;
#pragma unroll
            for (int i = 0; i < 8; i++) {
                s += sc[i];
                mx = max(mx, __float_as_uint(sc[i]));
            }
#pragma unroll
            for (int o = 16; o; o >>= 1)
                s += __shfl_down_sync(0xffffffffu, s, o);
            mx = __reduce_max_sync(0xffffffffu, mx);
            if (lane == 0) { s_bsum[warp] = s; s_bmax[warp] = mx; }
        }
        if (tid == 0) s_cnt = 0;
        __syncthreads();

        unsigned gbound = isHigh ? 0u : 0xFFFFFFFFu;
#pragma unroll
        for (int w = 0; w < 8; w++)
            gbound = isHigh ? max(gbound, s_r[w]) : min(gbound, s_r[w]);

        if (isHigh && tid == 0) {
            float s = 0.f;
            unsigned mx = 0u;
#pragma unroll
            for (int w = 0; w < 8; w++) { s += s_bsum[w]; mx = max(mx, s_bmax[w]); }
            g_psum[b] = s;
            g_pmax[b] = mx;
        }

        float lo, hi;
        if (isHigh) { hi = __uint_as_float(gbound); lo = hi - 0.3f; }
        else        { lo = __uint_as_float(gbound); hi = lo + 1e-9f; }

        int myT = 0;
#pragma unroll
        for (int i = 0; i < 8; i++) myT += (sc[i] >= lo && sc[i] <= hi);
        {
            int w = __reduce_add_sync(0xffffffffu, myT);
            if (lane == 0) s_red[warp] = w;
            __syncthreads();
            if (tid == 0) {
                int t = 0;
#pragma unroll
                for (int ww = 0; ww < 8; ww++) t += s_red[ww];
                s_red[0] = t;
            }
            __syncthreads();
        }
        int T = s_red[0];
        int kneed = isHigh ? KH : 10;
        int target = min(T, kneed);

        float hi2 = hi;
        if (isHigh && T > 0) {
            float delta = 0.3f * 24.f / (float)T;   // expect ~24 in band
            for (;;) {
                hi2 = fminf(hi, lo + delta);
                int mc = 0;
#pragma unroll
                for (int i = 0; i < 8; i++) mc += (sc[i] >= lo && sc[i] <= hi2);
                int w = __reduce_add_sync(0xffffffffu, mc);
                if (lane == 0) s_red[warp] = w;
                __syncthreads();
                if (tid == 0) {
                    int t = 0;
#pragma unroll
                    for (int ww = 0; ww < 8; ww++) t += s_red[ww];
                    s_red[1] = t;
                }
                __syncthreads();
                if (s_red[1] >= target || hi2 >= hi) break;
                delta *= 4.f;
                __syncthreads();
            }
        }

#pragma unroll
        for (int i = 0; i < 8; i++) {
            if (sc[i] >= lo && sc[i] <= hi2) {
                int pos = atomicAdd(&s_cnt, 1);
                s_list[pos] =
                    ((unsigned long long)__float_as_uint(sc[i]) << 32) |
                    (unsigned)(tid + i * 256);
            }
        }
        __syncthreads();
        int C = s_cnt;

        int labb = isHigh ? label[b] : 2;           // 2 = N_CLASSES
        if (isHigh) {
            if (tid < KH) {
                int r = b * KH + tid;
                g_lab[r] = labb;
                if (tid >= target) { g_val[r] = 0; g_idx[r] = 0; }
                else               { g_val[r] = 1; }
            }
        } else {
            int sl = (target + 1) >> 1;             // slots 0..sl-1 valid
            if (tid < KL) {
                int r = HROWS + b * KL + tid;
                g_lab[r] = 2;
                if (tid >= sl) { g_val[r] = 0; g_idx[r] = 0; }
                else           { g_val[r] = 1; }
            }
        }

        for (int i = tid; i < C; i += 256) {
            unsigned long long k = s_list[i];
            int r = 0;
            for (int j = 0; j < C; j++) r += (s_list[j] < k);
            int idx = b * N_ + (int)(k & 0xFFFFFFFFULL);
            if (isHigh) {
                if (r < KH) g_idx[b * KH + r] = idx;
            } else {
                if (r < 10 && !(r & 1)) g_idx[HROWS + b * KL + (r >> 1)] = idx;
            }
        }

        __syncthreads();
        if (tid == 0) {
            __threadfence();
            atomicAdd(&g_seldone, 1);
        }
    } else {
        // ================== gram GEMM (blocks 32..431) ==================
        if (tid == 0) {
            while (ld_cg(&g_seldone) < SELBLK) { __nanosleep(32); }
            __threadfence();
        }
        __syncthreads();

        int gb = bid - SELBLK;                 // 0..399
        int kz = gb & (SPLITK - 1), tile = gb / SPLITK;
        int bm = tile / 5, bn = tile % 5;
        int tx = tid & 15, ty = tid >> 4;
        int tx4 = tx * 4, ty4 = ty * 4;

        unsigned long long cc[4][2];
#pragma unroll
        for (int i = 0; i < 4; i++) { cc[i][0] = 0ULL; cc[i][1] = 0ULL; }

        int loadRow = tid >> 2;           // 0..63
        int loadK4  = (tid & 3) * 4;      // 0,4,8,12
        // indirect gather: invalid rows point at row 0; masked in loss phase
        const float* A0 = fea + (size_t)g_idx[bm * BM + loadRow] * D_ + kz * KC + loadK4;
        const float* B0 = fea + (size_t)g_idx[bn * BN + loadRow] * D_ + kz * KC + loadK4;

        float4 a = *(const float4*)A0;
        float4 b4 = *(const float4*)B0;
        As[0][loadK4 + 0][loadRow] = a.x;
        As[0][loadK4 + 1][loadRow] = a.y;
        As[0][loadK4 + 2][loadRow] = a.z;
        As[0][loadK4 + 3][loadRow] = a.w;
        Bs[0][loadK4 + 0][loadRow] = b4.x;
        Bs[0][loadK4 + 1][loadRow] = b4.y;
        Bs[0][loadK4 + 2][loadRow] = b4.z;
        Bs[0][loadK4 + 3][loadRow] = b4.w;
        __syncthreads();

#pragma unroll
        for (int it = 0; it < KC / BK; it++) {
            int cur = it & 1;
            if (it < KC / BK - 1) {                  // prefetch next slab
                a  = *(const float4*)(A0 + (it + 1) * BK);
                b4 = *(const float4*)(B0 + (it + 1) * BK);
            }
#pragma unroll
            for (int k = 0; k < BK; k++) {
                float4 av = *(const float4*)&As[cur][k][ty4];    // LDS.128
                float4 bv = *(const float4*)&Bs[cur][k][tx4];    // LDS.128
                unsigned long long bp0, bp1;
                asm("mov.b64 %0, {%1, %2};" : "=l"(bp0)
                    : "r"(__float_as_uint(bv.x)), "r"(__float_as_uint(bv.y)));
                asm("mov.b64 %0, {%1, %2};" : "=l"(bp1)
                    : "r"(__float_as_uint(bv.z)), "r"(__float_as_uint(bv.w)));
                unsigned long long A0d = dup_f32(av.x);
                unsigned long long A1d = dup_f32(av.y);
                unsigned long long A2d = dup_f32(av.z);
                unsigned long long A3d = dup_f32(av.w);
                cc[0][0] = f32x2_fma(cc[0][0], A0d, bp0);
                cc[0][1] = f32x2_fma(cc[0][1], A0d, bp1);
                cc[1][0] = f32x2_fma(cc[1][0], A1d, bp0);
                cc[1][1] = f32x2_fma(cc[1][1], A1d, bp1);
                cc[2][0] = f32x2_fma(cc[2][0], A2d, bp0);
                cc[2][1] = f32x2_fma(cc[2][1], A2d, bp1);
                cc[3][0] = f32x2_fma(cc[3][0], A3d, bp0);
                cc[3][1] = f32x2_fma(cc[3][1], A3d, bp1);
            }
            if (it < KC / BK - 1) {
                int nxt = cur ^ 1;
                As[nxt][loadK4 + 0][loadRow] = a.x;
                As[nxt][loadK4 + 1][loadRow] = a.y;
                As[nxt][loadK4 + 2][loadRow] = a.z;
                As[nxt][loadK4 + 3][loadRow] = a.w;
                Bs[nxt][loadK4 + 0][loadRow] = b4.x;
                Bs[nxt][loadK4 + 1][loadRow] = b4.y;
                Bs[nxt][loadK4 + 2][loadRow] = b4.z;
                Bs[nxt][loadK4 + 3][loadRow] = b4.w;
                __syncthreads();
            }
        }

        float* og = g_Gk[kz];
#pragma unroll
        for (int i = 0; i < 4; i++) {
            unsigned lo0, hi0, lo1, hi1;
            asm("mov.b64 {%0, %1}, %2;" : "=r"(lo0), "=r"(hi0) : "l"(cc[i][0]));
            asm("mov.b64 {%0, %1}, %2;" : "=r"(lo1), "=r"(hi1) : "l"(cc[i][1]));
            float4 v = make_float4(__uint_as_float(lo0), __uint_as_float(hi0),
                                   __uint_as_float(lo1), __uint_as_float(hi1));
            int row = bm * BM + ty4 + i;
            *(float4*)(og + (size_t)row * ROWS + bn * BN + tx4) = v;
        }

        // release this task into its row-stripe counter
        __syncthreads();
        if (tid == 0) {
            __threadfence();
            atomicAdd(&g_rowcnt[bm], 1);
        }
    }

    // ================== loss phase (blocks 0-319, one query each) ==========
    if (bid < ROWS) {
        int q = bid;
        int qt = q >> 6;                 // row-stripe of this query
        if (tid == 0) {
            while (ld_cg(&g_rowcnt[qt]) < TASKS_PER_ROW) { __nanosleep(32); }
            __threadfence();
        }
        __syncthreads();

        int labq = g_lab[q];
        float den = 0.f, num = 0.f;
        for (int n = tid; n < ROWS; n += 256) {
            float g = 0.f;
#pragma unroll
            for (int s = 0; s < SPLITK; s++) g += g_Gk[s][q * ROWS + n];
            float e = __expf(g * 0.0625f);          // TAU = 16
            e = g_val[n] ? e : 0.f;
            den += e;
            if (g_lab[n] == labq) num += e;
        }
#pragma unroll
        for (int o = 16; o; o >>= 1) {
            den += __shfl_down_sync(0xffffffffu, den, o);
            num += __shfl_down_sync(0xffffffffu, num, o);
        }
        if (lane == 0) { red[warp] = den; red[8 + warp] = num; }
        __syncthreads();
        if (tid == 0) {
            float d = 0.f, nm = 0.f;
#pragma unroll
            for (int w = 0; w < 8; w++) { d += red[w]; nm += red[8 + w]; }
            g_per[q] = g_val[q] ? -__logf(nm / d) : 0.f;
        }
    }

    // ================== completion counter over ALL blocks =================
    __syncthreads();
    if (tid == 0) {
        __threadfence();
        int o = atomicAdd(&g_cnt, 1);
        s_last = (o == GRID_ - 1);     // globally last -> all g_per visible
    }
    __syncthreads();

    if (s_last) {
        __threadfence();
        if (tid < B_) {
            int b = tid;
            float s = 0.f; int c = 0;
            for (int k = 0; k < KH; k++) { int r = b * KH + k; s += g_per[r]; c += g_val[r]; }
            for (int k = 0; k < KL; k++) { int r = HROWS + b * KL + k; s += g_per[r]; c += g_val[r]; }
            s_c[b] = s / (float)c;
            float se = __expf(ori[b * 2 + 0]) + __expf(ori[b * 2 + 1]);
            s_ce[b] = -__logf(__expf(t_logit[0]) / se);
        }
        __syncthreads();
        if (tid == 0) {
            float contr = 0.f, ce = 0.f;
#pragma unroll
            for (int b = 0; b < B_; b++) { contr += s_c[b]; ce += s_ce[b]; }
            contr /= (float)B_;
            ce /= (float)B_;

            unsigned mx = 0u;
            float sum = 0.f;
#pragma unroll
            for (int i = 0; i < B_; i++) { mx = max(mx, g_pmax[i]); sum += g_psum[i]; }
            float gmax = __uint_as_float(mx);
            float meanv = sum / (float)(B_ * N_);
            float Dm = meanv / gmax;
            float l2 = 0.0001f * (1.f - Dm) * (1.f - Dm) * l2w[0];

            out[0] = contr + ce + l2;
            // everyone has passed g_seldone and g_rowcnt -> safe to reset:
            g_seldone = 0;
#pragma unroll
            for (int i = 0; i < 5; i++) g_rowcnt[i] = 0;
            g_cnt = 0;
            __threadfence();
        }
    }
}

// ---------------- launch ----------------
extern "C" void kernel_launch(void* const* d_in, const int* in_sizes, int n_in,
                              void* d_out, int out_size) {
    const float* fea     = (const float*)d_in[0];
    const float* score   = (const float*)d_in[1];
    const int*   label   = (const int*)d_in[2];
    const float* t_logit = (const float*)d_in[3];
    const float* ori     = (const float*)d_in[4];
    const float* l2w     = (const float*)d_in[5];
    float* out = (float*)d_out;

    k_all<<<GRID_, 256>>>(fea, score, label, t_logit, ori, l2w, out);
}

// round 16
// speedup vs baseline: 1.3689x; 1.0960x over previous
#include <cuda_runtime.h>

#define B_    16
#define N_    2048
#define D_    1024
#define KH    15
#define KL    5
#define ROWS  320      // B_*KH + B_*KL
#define HROWS 240      // B_*KH
#define SPLITK 16
#define KC    (D_ / SPLITK)   // 64

#define BM 64
#define BN 64
#define BK 16
#define SELBLK 32
#define NTILE 15                           // upper-triangle 5x5 tiles
#define GEMMTASKS (NTILE * SPLITK)         // 240
#define GRID_ 320                          // >= max(SELBLK+GEMMTASKS, ROWS)
#define LCAP 2048                          // >= bag size: gather can't overflow
#define TASKS_PER_ROW (5 * SPLITK)         // 80 writes complete a 64-row stripe

// upper-triangle tile map (bm <= bn)
__device__ __constant__ int TBM[NTILE] = {0,0,0,0,0,1,1,1,1,2,2,2,3,3,4};
__device__ __constant__ int TBN[NTILE] = {0,1,2,3,4,1,2,3,4,2,3,4,3,4,4};

// ---------------- scratch (no allocations allowed) ----------------
__device__ unsigned int g_pmax[B_];
__device__ float        g_psum[B_];
__device__ int          g_idx[ROWS];
__device__ int          g_val[ROWS];
__device__ int          g_lab[ROWS];
__device__ __align__(16) float g_Gk[SPLITK][ROWS * ROWS];
__device__ float        g_per[ROWS];
__device__ int          g_seldone;    // selection-ready counter
__device__ int          g_rowcnt[5];  // per-64-row-stripe GEMM completion
__device__ int          g_cnt;        // completion counter (ALL blocks)

// ---------------- helpers ----------------
__device__ __forceinline__ unsigned long long f32x2_fma(unsigned long long c,
                                                        unsigned long long a,
                                                        unsigned long long b) {
    asm("fma.rn.f32x2 %0, %1, %2, %0;" : "+l"(c) : "l"(a), "l"(b));
    return c;
}

__device__ __forceinline__ unsigned long long dup_f32(float x) {
    unsigned long long r;
    unsigned u = __float_as_uint(x);
    asm("mov.b64 %0, {%1, %1};" : "=l"(r) : "r"(u));
    return r;
}

__device__ __forceinline__ int ld_cg(const int* p) {
    int v;
    asm volatile("ld.global.cg.b32 %0, [%1];" : "=r"(v) : "l"(p));
    return v;
}

// ===== ONE kernel: selection (0-31) | symmetric gemm (32-271) | per-stripe
//       release | loss (0-319) | last-block final scalar.
// G = X X^T is symmetric: only bm<=bn tiles are computed; off-diagonal tasks
// write both the tile and its transpose, so each 64-row stripe still receives
// exactly 80 task-writes (direct 5-bm + mirrored bm). Selection is
// barrier-free counting-rank (R13, proven).
__global__ void __launch_bounds__(256, 3)
k_all(const float* __restrict__ fea, const float* __restrict__ score,
      const int* __restrict__ label, const float* __restrict__ t_logit,
      const float* __restrict__ ori, const float* __restrict__ l2w,
      float* __restrict__ out) {
    __shared__ __align__(16) float As[2][BK][BM + 4];
    __shared__ __align__(16) float Bs[2][BK][BN + 4];
    __shared__ unsigned long long s_list[LCAP];
    __shared__ unsigned s_r[8];
    __shared__ float    s_bsum[8];
    __shared__ unsigned s_bmax[8];
    __shared__ int      s_red[8];
    __shared__ int      s_cnt;
    __shared__ float    red[16];
    __shared__ int      s_last;
    __shared__ float    s_c[B_], s_ce[B_];
    int bid = blockIdx.x, tid = threadIdx.x;
    int lane = tid & 31, warp = tid >> 5;

    if (bid < SELBLK) {
        // ================== selection (R13 counting-rank) ==================
        bool isHigh = bid < B_;
        int b = isHigh ? bid : bid - B_;

        const float4* s4 = (const float4*)score;
        unsigned gbv = isHigh ? 0u : 0xFFFFFFFFu;   // score >= 0 -> bits monotonic
#pragma unroll 16
        for (int i = 0; i < (B_ * N_ / 4) / 256; i++) {  // 32 float4 / thread
            float4 v = s4[tid + i * 256];
            unsigned b0 = __float_as_uint(v.x), b1 = __float_as_uint(v.y);
            unsigned b2 = __float_as_uint(v.z), b3 = __float_as_uint(v.w);
            if (isHigh) gbv = max(max(gbv, b0), max(b1, max(b2, b3)));
            else        gbv = min(min(gbv, b0), min(b1, min(b2, b3)));
        }
        gbv = isHigh ? __reduce_max_sync(0xffffffffu, gbv)
                     : __reduce_min_sync(0xffffffffu, gbv);
        if (lane == 0) s_r[warp] = gbv;

        float sc[8];
#pragma unroll
        for (int i = 0; i < 8; i++) sc[i] = score[b * N_ + tid + i * 256];

        if (isHigh) {
            float s = 0.f;
            unsigned mx = 0u;
#pragma unroll
            for (int i = 0; i < 8; i++) {
                s += sc[i];
                mx = max(mx, __float_as_uint(sc[i]));
            }
#pragma unroll
            for (int o = 16; o; o >>= 1)
                s += __shfl_down_sync(0xffffffffu, s, o);
            mx = __reduce_max_sync(0xffffffffu, mx);
            if (lane == 0) { s_bsum[warp] = s; s_bmax[warp] = mx; }
        }
        if (tid == 0) s_cnt = 0;
        __syncthreads();

        unsigned gbound = isHigh ? 0u : 0xFFFFFFFFu;
#pragma unroll
        for (int w = 0; w < 8; w++)
            gbound = isHigh ? max(gbound, s_r[w]) : min(gbound, s_r[w]);

        if (isHigh && tid == 0) {
            float s = 0.f;
            unsigned mx = 0u;
#pragma unroll
            for (int w = 0; w < 8; w++) { s += s_bsum[w]; mx = max(mx, s_bmax[w]); }
            g_psum[b] = s;
            g_pmax[b] = mx;
        }

        float lo, hi;
        if (isHigh) { hi = __uint_as_float(gbound); lo = hi - 0.3f; }
        else        { lo = __uint_as_float(gbound); hi = lo + 1e-9f; }

        int myT = 0;
#pragma unroll
        for (int i = 0; i < 8; i++) myT += (sc[i] >= lo && sc[i] <= hi);
        {
            int w = __reduce_add_sync(0xffffffffu, myT);
            if (lane == 0) s_red[warp] = w;
            __syncthreads();
            if (tid == 0) {
                int t = 0;
#pragma unroll
                for (int ww = 0; ww < 8; ww++) t += s_red[ww];
                s_red[0] = t;
            }
            __syncthreads();
        }
        int T = s_red[0];
        int kneed = isHigh ? KH : 10;
        int target = min(T, kneed);

        float hi2 = hi;
        if (isHigh && T > 0) {
            float delta = 0.3f * 24.f / (float)T;   // expect ~24 in band
            for (;;) {
                hi2 = fminf(hi, lo + delta);
                int mc = 0;
#pragma unroll
                for (int i = 0; i < 8; i++) mc += (sc[i] >= lo && sc[i] <= hi2);
                int w = __reduce_add_sync(0xffffffffu, mc);
                if (lane == 0) s_red[warp] = w;
                __syncthreads();
                if (tid == 0) {
                    int t = 0;
#pragma unroll
                    for (int ww = 0; ww < 8; ww++) t += s_red[ww];
                    s_red[1] = t;
                }
                __syncthreads();
                if (s_red[1] >= target || hi2 >= hi) break;
                delta *= 4.f;
                __syncthreads();
            }
        }

#pragma unroll
        for (int i = 0; i < 8; i++) {
            if (sc[i] >= lo && sc[i] <= hi2) {
                int pos = atomicAdd(&s_cnt, 1);
                s_list[pos] =
                    ((unsigned long long)__float_as_uint(sc[i]) << 32) |
                    (unsigned)(tid + i * 256);
            }
        }
        __syncthreads();
        int C = s_cnt;

        int labb = isHigh ? label[b] : 2;           // 2 = N_CLASSES
        if (isHigh) {
            if (tid < KH) {
                int r = b * KH + tid;
                g_lab[r] = labb;
                if (tid >= target) { g_val[r] = 0; g_idx[r] = 0; }
                else               { g_val[r] = 1; }
            }
        } else {
            int sl = (target + 1) >> 1;             // slots 0..sl-1 valid
            if (tid < KL) {
                int r = HROWS + b * KL + tid;
                g_lab[r] = 2;
                if (tid >= sl) { g_val[r] = 0; g_idx[r] = 0; }
                else           { g_val[r] = 1; }
            }
        }

        for (int i = tid; i < C; i += 256) {
            unsigned long long k = s_list[i];
            int r = 0;
            for (int j = 0; j < C; j++) r += (s_list[j] < k);
            int idx = b * N_ + (int)(k & 0xFFFFFFFFULL);
            if (isHigh) {
                if (r < KH) g_idx[b * KH + r] = idx;
            } else {
                if (r < 10 && !(r & 1)) g_idx[HROWS + b * KL + (r >> 1)] = idx;
            }
        }

        __syncthreads();
        if (tid == 0) {
            __threadfence();
            atomicAdd(&g_seldone, 1);
        }
    } else if (bid < SELBLK + GEMMTASKS) {
        // ======== symmetric gram GEMM (blocks 32..271, bm<=bn tiles) ========
        if (tid == 0) {
            while (ld_cg(&g_seldone) < SELBLK) { __nanosleep(32); }
            __threadfence();
        }
        __syncthreads();

        int gb = bid - SELBLK;                 // 0..239
        int kz = gb & (SPLITK - 1), tile = gb / SPLITK;
        int bm = TBM[tile], bn = TBN[tile];
        int tx = tid & 15, ty = tid >> 4;
        int tx4 = tx * 4, ty4 = ty * 4;

        unsigned long long cc[4][2];
#pragma unroll
        for (int i = 0; i < 4; i++) { cc[i][0] = 0ULL; cc[i][1] = 0ULL; }

        int loadRow = tid >> 2;           // 0..63
        int loadK4  = (tid & 3) * 4;      // 0,4,8,12
        // indirect gather: invalid rows point at row 0; masked in loss phase
        const float* A0 = fea + (size_t)g_idx[bm * BM + loadRow] * D_ + kz * KC + loadK4;
        const float* B0 = fea + (size_t)g_idx[bn * BN + loadRow] * D_ + kz * KC + loadK4;

        float4 a = *(const float4*)A0;
        float4 b4 = *(const float4*)B0;
        As[0][loadK4 + 0][loadRow] = a.x;
        As[0][loadK4 + 1][loadRow] = a.y;
        As[0][loadK4 + 2][loadRow] = a.z;
        As[0][loadK4 + 3][loadRow] = a.w;
        Bs[0][loadK4 + 0][loadRow] = b4.x;
        Bs[0][loadK4 + 1][loadRow] = b4.y;
        Bs[0][loadK4 + 2][loadRow] = b4.z;
        Bs[0][loadK4 + 3][loadRow] = b4.w;
        __syncthreads();

#pragma unroll
        for (int it = 0; it < KC / BK; it++) {
            int cur = it & 1;
            if (it < KC / BK - 1) {                  // prefetch next slab
                a  = *(const float4*)(A0 + (it + 1) * BK);
                b4 = *(const float4*)(B0 + (it + 1) * BK);
            }
#pragma unroll
            for (int k = 0; k < BK; k++) {
                float4 av = *(const float4*)&As[cur][k][ty4];    // LDS.128
                float4 bv = *(const float4*)&Bs[cur][k][tx4];    // LDS.128
                unsigned long long bp0, bp1;
                asm("mov.b64 %0, {%1, %2};" : "=l"(bp0)
                    : "r"(__float_as_uint(bv.x)), "r"(__float_as_uint(bv.y)));
                asm("mov.b64 %0, {%1, %2};" : "=l"(bp1)
                    : "r"(__float_as_uint(bv.z)), "r"(__float_as_uint(bv.w)));
                unsigned long long A0d = dup_f32(av.x);
                unsigned long long A1d = dup_f32(av.y);
                unsigned long long A2d = dup_f32(av.z);
                unsigned long long A3d = dup_f32(av.w);
                cc[0][0] = f32x2_fma(cc[0][0], A0d, bp0);
                cc[0][1] = f32x2_fma(cc[0][1], A0d, bp1);
                cc[1][0] = f32x2_fma(cc[1][0], A1d, bp0);
                cc[1][1] = f32x2_fma(cc[1][1], A1d, bp1);
                cc[2][0] = f32x2_fma(cc[2][0], A2d, bp0);
                cc[2][1] = f32x2_fma(cc[2][1], A2d, bp1);
                cc[3][0] = f32x2_fma(cc[3][0], A3d, bp0);
                cc[3][1] = f32x2_fma(cc[3][1], A3d, bp1);
            }
            if (it < KC / BK - 1) {
                int nxt = cur ^ 1;
                As[nxt][loadK4 + 0][loadRow] = a.x;
                As[nxt][loadK4 + 1][loadRow] = a.y;
                As[nxt][loadK4 + 2][loadRow] = a.z;
                As[nxt][loadK4 + 3][loadRow] = a.w;
                Bs[nxt][loadK4 + 0][loadRow] = b4.x;
                Bs[nxt][loadK4 + 1][loadRow] = b4.y;
                Bs[nxt][loadK4 + 2][loadRow] = b4.z;
                Bs[nxt][loadK4 + 3][loadRow] = b4.w;
                __syncthreads();
            }
        }

        // unpack accumulators
        float v[4][4];
#pragma unroll
        for (int i = 0; i < 4; i++) {
            unsigned lo0, hi0, lo1, hi1;
            asm("mov.b64 {%0, %1}, %2;" : "=r"(lo0), "=r"(hi0) : "l"(cc[i][0]));
            asm("mov.b64 {%0, %1}, %2;" : "=r"(lo1), "=r"(hi1) : "l"(cc[i][1]));
            v[i][0] = __uint_as_float(lo0);
            v[i][1] = __uint_as_float(hi0);
            v[i][2] = __uint_as_float(lo1);
            v[i][3] = __uint_as_float(hi1);
        }

        float* og = g_Gk[kz];
        // direct tile (coalesced)
#pragma unroll
        for (int i = 0; i < 4; i++) {
            int row = bm * BM + ty4 + i;
            *(float4*)(og + (size_t)row * ROWS + bn * BN + tx4) =
                make_float4(v[i][0], v[i][1], v[i][2], v[i][3]);
        }
        // mirror tile (transposed) for off-diagonal tasks
        if (bm != bn) {
#pragma unroll
            for (int j = 0; j < 4; j++) {
                int row = bn * BN + tx4 + j;
                *(float4*)(og + (size_t)row * ROWS + bm * BM + ty4) =
                    make_float4(v[0][j], v[1][j], v[2][j], v[3][j]);
            }
        }

        // release this task into its row-stripe counter(s)
        __syncthreads();
        if (tid == 0) {
            __threadfence();
            atomicAdd(&g_rowcnt[bm], 1);
            if (bm != bn) atomicAdd(&g_rowcnt[bn], 1);
        }
    }

    // ================== loss phase (blocks 0-319, one query each) ==========
    if (bid < ROWS) {
        int q = bid;
        int qt = q >> 6;                 // row-stripe of this query
        if (tid == 0) {
            while (ld_cg(&g_rowcnt[qt]) < TASKS_PER_ROW) { __nanosleep(32); }
            __threadfence();
        }
        __syncthreads();

        int labq = g_lab[q];
        float den = 0.f, num = 0.f;
        for (int n = tid; n < ROWS; n += 256) {
            float g = 0.f;
#pragma unroll
            for (int s = 0; s < SPLITK; s++) g += g_Gk[s][q * ROWS + n];
            float e = __expf(g * 0.0625f);          // TAU = 16
            e = g_val[n] ? e : 0.f;
            den += e;
            if (g_lab[n] == labq) num += e;
        }
#pragma unroll
        for (int o = 16; o; o >>= 1) {
            den += __shfl_down_sync(0xffffffffu, den, o);
            num += __shfl_down_sync(0xffffffffu, num, o);
        }
        if (lane == 0) { red[warp] = den; red[8 + warp] = num; }
        __syncthreads();
        if (tid == 0) {
            float d = 0.f, nm = 0.f;
#pragma unroll
            for (int w = 0; w < 8; w++) { d += red[w]; nm += red[8 + w]; }
            g_per[q] = g_val[q] ? -__logf(nm / d) : 0.f;
        }
    }

    // ================== completion counter over ALL blocks =================
    __syncthreads();
    if (tid == 0) {
        __threadfence();
        int o = atomicAdd(&g_cnt, 1);
        s_last = (o == GRID_ - 1);     // globally last -> all g_per visible
    }
    __syncthreads();

    if (s_last) {
        __threadfence();
        if (tid < B_) {
            int b = tid;
            float s = 0.f; int c = 0;
            for (int k = 0; k < KH; k++) { int r = b * KH + k; s += g_per[r]; c += g_val[r]; }
            for (int k = 0; k < KL; k++) { int r = HROWS + b * KL + k; s += g_per[r]; c += g_val[r]; }
            s_c[b] = s / (float)c;
            float se = __expf(ori[b * 2 + 0]) + __expf(ori[b * 2 + 1]);
            s_ce[b] = -__logf(__expf(t_logit[0]) / se);
        }
        __syncthreads();
        if (tid == 0) {
            float contr = 0.f, ce = 0.f;
#pragma unroll
            for (int b = 0; b < B_; b++) { contr += s_c[b]; ce += s_ce[b]; }
            contr /= (float)B_;
            ce /= (float)B_;

            unsigned mx = 0u;
            float sum = 0.f;
#pragma unroll
            for (int i = 0; i < B_; i++) { mx = max(mx, g_pmax[i]); sum += g_psum[i]; }
            float gmax = __uint_as_float(mx);
            float meanv = sum / (float)(B_ * N_);
            float Dm = meanv / gmax;
            float l2 = 0.0001f * (1.f - Dm) * (1.f - Dm) * l2w[0];

            out[0] = contr + ce + l2;
            // everyone has passed g_seldone and g_rowcnt -> safe to reset:
            g_seldone = 0;
#pragma unroll
            for (int i = 0; i < 5; i++) g_rowcnt[i] = 0;
            g_cnt = 0;
            __threadfence();
        }
    }
}

// ---------------- launch ----------------
extern "C" void kernel_launch(void* const* d_in, const int* in_sizes, int n_in,
                              void* d_out, int out_size) {
    const float* fea     = (const float*)d_in[0];
    const float* score   = (const float*)d_in[1];
    const int*   label   = (const int*)d_in[2];
    const float* t_logit = (const float*)d_in[3];
    const float* ori     = (const float*)d_in[4];
    const float* l2w     = (const float*)d_in[5];
    float* out = (float*)d_out;

    k_all<<<GRID_, 256>>>(fea, score, label, t_logit, ori, l2w, out);
}